// round 12
// baseline (speedup 1.0000x reference)
#include <cuda_runtime.h>

#define NN     2048
#define IN_F   512
#define HID    256
#define OUT_F  128
#define H1     8
#define NWORDS 64   // NN/32
#define JS1    4    // agg1 j-split
#define JS2    8    // agg2 j-split
#define KS1G   2    // gemm1 K-split
#define KS2G   4    // gemm2 K-split

typedef unsigned u32;

// pack {lo, hi} floats into bf16x2 (element0 = lo)
__device__ __forceinline__ u32 packbf(float lo, float hi) {
    u32 d; asm("cvt.rn.bf16x2.f32 %0, %1, %2;" : "=r"(d) : "f"(hi), "f"(lo)); return d;
}
__device__ __forceinline__ float bf_lo(u32 p) { return __uint_as_float(p << 16); }
__device__ __forceinline__ float bf_hi(u32 p) { return __uint_as_float(p & 0xffff0000u); }

__device__ __forceinline__ void mma16(float* d, const u32* a, u32 b0, u32 b1) {
    asm volatile(
        "mma.sync.aligned.m16n8k16.row.col.f32.bf16.bf16.f32 "
        "{%0,%1,%2,%3}, {%4,%5,%6,%7}, {%8,%9}, {%0,%1,%2,%3};"
        : "+f"(d[0]), "+f"(d[1]), "+f"(d[2]), "+f"(d[3])
        : "r"(a[0]), "r"(a[1]), "r"(a[2]), "r"(a[3]), "r"(b0), "r"(b1));
}
__device__ __forceinline__ void cpa16(u32 s, const void* g) {
    asm volatile("cp.async.ca.shared.global [%0], [%1], 16;" :: "r"(s), "l"(g));
}
#define CP_COMMIT asm volatile("cp.async.commit_group;")
#define CP_WAIT1  asm volatile("cp.async.wait_group 1;")
#define CP_WAIT0  asm volatile("cp.async.wait_group 0;")

// ---------------- scratch ----------------
__device__ __align__(16) float4 g_xAh[128 * 32 * 32];   // x A-frag hi (2MB)
__device__ __align__(16) float4 g_xAl[128 * 32 * 32];
__device__ __align__(16) float4 g_w1B[32 * 32 * 32];    // W1 B-frags
__device__ __align__(16) float4 g_w2B[16 * 16 * 32];    // W2 B-frags
__device__ __align__(16) float  g_gp1[KS1G * NN * HID];
__device__ __align__(16) float4 g_eli1t[H1 * NN];   // [h][i] {-el, exp(el), exp(0.2el), 0}
__device__ __align__(16) float4 g_ebd1t[H1 * NN];   // [h][j]
__device__ __align__(16) float4 g_frag1[H1 * 128 * 4 * 32];   // agg1 bf16 B-frags (2MB)
__device__ unsigned g_bits[NN * NWORDS];
__device__ __align__(16) float  g_n1[JS1 * NN * HID];
__device__ float  g_d1[JS1 * NN * H1];
__device__ __align__(16) float4 g_h1Ah[128 * 16 * 32];  // h1 A-frags hi (1MB)
__device__ __align__(16) float4 g_h1Al[128 * 16 * 32];
__device__ __align__(16) float  g_gp2[KS2G * NN * OUT_F];
__device__ __align__(16) float4 g_eli2[NN];
__device__ __align__(16) float4 g_ebd2[NN];
__device__ __align__(16) float4 g_frag2[128 * 4 * 128];       // agg2 bf16 B-frags (1MB)
__device__ __align__(16) float  g_part[JS2 * NN * OUT_F];
__device__ float  g_psum[JS2 * NN];

// ---------------- prep0: pack adjacency (blocks < NN) + input fragments ----------------
__global__ void prep0_kernel(const int* __restrict__ adj, const float* __restrict__ x,
                             const float* __restrict__ W1, const float* __restrict__ W2) {
    int t = threadIdx.x;  // 256
    if (blockIdx.x < NN) {
        int i = blockIdx.x;
        const int* row = adj + (size_t)i * NN;
#pragma unroll
        for (int k = 0; k < 8; k++) {
            int j = k * 256 + t;
            unsigned b = __ballot_sync(0xffffffffu, row[j] != 0);
            if ((t & 31) == 0) g_bits[i * NWORDS + (j >> 5)] = b;
        }
        return;
    }
    int idx = (blockIdx.x - NN) * 256 + t;   // < 172032
    if (idx < 131072) {
        int lane = idx & 31, kt = (idx >> 5) & 31, it = idx >> 10;
        int g = lane >> 2, tq = lane & 3;
        int r = it * 16 + g, c = kt * 16 + 2 * tq;
        const float* xr = x + (size_t)r * IN_F + c;
        float2 p0 = *(const float2*)xr;
        float2 p1 = *(const float2*)(xr + 8 * IN_F);
        float2 p2 = *(const float2*)(xr + 8);
        float2 p3 = *(const float2*)(xr + 8 * IN_F + 8);
        u32 a0 = packbf(p0.x, p0.y), a1 = packbf(p1.x, p1.y);
        u32 a2 = packbf(p2.x, p2.y), a3 = packbf(p3.x, p3.y);
        g_xAh[idx] = make_float4(__uint_as_float(a0), __uint_as_float(a1),
                                 __uint_as_float(a2), __uint_as_float(a3));
        u32 l0 = packbf(p0.x - bf_lo(a0), p0.y - bf_hi(a0));
        u32 l1 = packbf(p1.x - bf_lo(a1), p1.y - bf_hi(a1));
        u32 l2 = packbf(p2.x - bf_lo(a2), p2.y - bf_hi(a2));
        u32 l3 = packbf(p3.x - bf_lo(a3), p3.y - bf_hi(a3));
        g_xAl[idx] = make_float4(__uint_as_float(l0), __uint_as_float(l1),
                                 __uint_as_float(l2), __uint_as_float(l3));
    } else if (idx < 163840) {
        int e = idx - 131072;                   // < 32768
        int lane = e & 31, nt = (e >> 5) & 31, kt = e >> 10;
        int g = lane >> 2, tq = lane & 3;
        int n = nt * 8 + g, k0 = kt * 16 + 2 * tq;
        float b0a = W1[(size_t)k0 * HID + n];
        float b0b = W1[(size_t)(k0 + 1) * HID + n];
        float b1a = W1[(size_t)(k0 + 8) * HID + n];
        float b1b = W1[(size_t)(k0 + 9) * HID + n];
        u32 bh0 = packbf(b0a, b0b), bh1 = packbf(b1a, b1b);
        u32 bl0 = packbf(b0a - bf_lo(bh0), b0b - bf_hi(bh0));
        u32 bl1 = packbf(b1a - bf_lo(bh1), b1b - bf_hi(bh1));
        g_w1B[e] = make_float4(__uint_as_float(bh0), __uint_as_float(bh1),
                               __uint_as_float(bl0), __uint_as_float(bl1));
    } else {
        int e = idx - 163840;                   // < 8192
        int lane = e & 31, nt = (e >> 5) & 15, kt = e >> 9;
        int g = lane >> 2, tq = lane & 3;
        int n = nt * 8 + g, k0 = kt * 16 + 2 * tq;
        float b0a = W2[(size_t)k0 * OUT_F + n];
        float b0b = W2[(size_t)(k0 + 1) * OUT_F + n];
        float b1a = W2[(size_t)(k0 + 8) * OUT_F + n];
        float b1b = W2[(size_t)(k0 + 9) * OUT_F + n];
        u32 bh0 = packbf(b0a, b0b), bh1 = packbf(b1a, b1b);
        u32 bl0 = packbf(b0a - bf_lo(bh0), b0b - bf_hi(bh0));
        u32 bl1 = packbf(b1a - bf_lo(bh1), b1b - bf_hi(bh1));
        g_w2B[e] = make_float4(__uint_as_float(bh0), __uint_as_float(bh1),
                               __uint_as_float(bl0), __uint_as_float(bl1));
    }
}

// ---------------- gemm1 bf16 tensor: 64i x 64n per block, K-split 2 ----------------
__global__ __launch_bounds__(256) void gemm1_mma_kernel() {
    __shared__ __align__(16) float4 Ah_s[2][4][2][32];
    __shared__ __align__(16) float4 Al_s[2][4][2][32];
    __shared__ __align__(16) float4 Bb_s[2][2][8][32];
    int z = blockIdx.z;
    int bi_t = blockIdx.y * 4;
    int bn_t = blockIdx.x * 8;
    int t = threadIdx.x;
    int lane = t & 31, w = t >> 5;
    int itw = w >> 1, nh = w & 1;
    float acc[4][4] = {};
    int ktz = z * 16;

#define GM_STAGE(b, ch) do { \
        int kt0 = ktz + (ch) * 2; \
        { int e = t; int ln = e & 31, kk = (e >> 5) & 1, it = e >> 6; \
          size_t gi = ((size_t)(bi_t + it) * 32 + kt0 + kk) * 32 + ln; \
          cpa16((u32)__cvta_generic_to_shared(&Ah_s[b][it][kk][ln]), g_xAh + gi); \
          cpa16((u32)__cvta_generic_to_shared(&Al_s[b][it][kk][ln]), g_xAl + gi); } \
        _Pragma("unroll") \
        for (int q = 0; q < 2; q++) { int e = t + q * 256; \
          int ln = e & 31, nt = (e >> 5) & 7, kk = e >> 8; \
          size_t gb = ((size_t)(kt0 + kk) * 32 + bn_t + nt) * 32 + ln; \
          cpa16((u32)__cvta_generic_to_shared(&Bb_s[b][kk][nt][ln]), g_w1B + gb); } \
    } while (0)

    GM_STAGE(0, 0);
    CP_COMMIT;
    for (int ch = 0; ch < 8; ch++) {
        int b = ch & 1;
        if (ch + 1 < 8) {
            GM_STAGE(b ^ 1, ch + 1);
            CP_COMMIT;
            CP_WAIT1;
        } else {
            CP_WAIT0;
        }
        __syncthreads();
#pragma unroll
        for (int kt = 0; kt < 2; kt++) {
            float4 a4h = Ah_s[b][itw][kt][lane];
            float4 a4l = Al_s[b][itw][kt][lane];
            u32 ah[4] = {__float_as_uint(a4h.x), __float_as_uint(a4h.y),
                         __float_as_uint(a4h.z), __float_as_uint(a4h.w)};
            u32 alr[4] = {__float_as_uint(a4l.x), __float_as_uint(a4l.y),
                          __float_as_uint(a4l.z), __float_as_uint(a4l.w)};
#pragma unroll
            for (int n4 = 0; n4 < 4; n4++) {
                float4 bb = Bb_s[b][kt][nh * 4 + n4][lane];
                u32 bh0 = __float_as_uint(bb.x), bh1 = __float_as_uint(bb.y);
                u32 bl0 = __float_as_uint(bb.z), bl1 = __float_as_uint(bb.w);
                mma16(acc[n4], ah, bh0, bh1);
                mma16(acc[n4], ah, bl0, bl1);
                mma16(acc[n4], alr, bh0, bh1);
            }
        }
        __syncthreads();
    }
    int g = lane >> 2, tq = lane & 3;
    int r0 = blockIdx.y * 64 + itw * 16 + g;
    float* Cz = g_gp1 + (size_t)z * NN * HID;
#pragma unroll
    for (int n4 = 0; n4 < 4; n4++) {
        int c = blockIdx.x * 64 + (nh * 4 + n4) * 8 + tq * 2;
        *(float2*)(Cz + (size_t)r0 * HID + c) = make_float2(acc[n4][0], acc[n4][1]);
        *(float2*)(Cz + (size_t)(r0 + 8) * HID + c) = make_float2(acc[n4][2], acc[n4][3]);
    }
}

// ---------------- elr1f: per-(jt, head-pair) fused partial-sum + el/er + frag emit ----------------
__global__ __launch_bounds__(256) void elr1f_kernel(const float* __restrict__ al,
                                                    const float* __restrict__ ar) {
    __shared__ float v_s[2][16][32];
    __shared__ float elb[2][16], erb[2][16];
    int jt = blockIdx.x;       // 128
    int base = jt * 16;
    int t = threadIdx.x;       // 256
    int hl = t >> 7;           // local head 0/1
    int tt = t & 127;
    int h = blockIdx.y * 2 + hl;  // 0..7
    int f = tt & 31, wr = tt >> 5;
    float alv = al[f], arv = ar[f];
#pragma unroll
    for (int s4 = 0; s4 < 4; s4++) {
        int node = wr * 4 + s4;
        float x = 0.f;
#pragma unroll
        for (int z = 0; z < KS1G; z++)
            x += g_gp1[((size_t)z * NN + base + node) * HID + h * 32 + f];
        v_s[hl][node][f] = x;
        float pl = x * alv, pr = x * arv;
#pragma unroll
        for (int o = 16; o; o >>= 1) {
            pl += __shfl_down_sync(0xffffffffu, pl, o);
            pr += __shfl_down_sync(0xffffffffu, pr, o);
        }
        if (f == 0) { elb[hl][node] = pl; erb[hl][node] = pr; }
    }
    __syncthreads();
    if (t < 32) {
        int hl2 = t >> 4, s = t & 15;
        int hh = blockIdx.y * 2 + hl2;
        float el = elb[hl2][s], er = erb[hl2][s];
        g_eli1t[hh * NN + base + s] = make_float4(-el, __expf(el), __expf(0.2f * el), 0.f);
        g_ebd1t[hh * NN + base + s] = make_float4(er, __expf(er), __expf(0.2f * er), 0.f);
    }
    int tq = tt >> 5, ff = tt & 31;
    float v0 = v_s[hl][2 * tq][ff];
    float v1 = v_s[hl][2 * tq + 1][ff];
    float v2 = v_s[hl][2 * tq + 8][ff];
    float v3 = v_s[hl][2 * tq + 9][ff];
    u32 bh0 = packbf(v0, v1), bh1 = packbf(v2, v3);
    u32 bl0 = packbf(v0 - bf_lo(bh0), v1 - bf_hi(bh0));
    u32 bl1 = packbf(v2 - bf_lo(bh1), v3 - bf_hi(bh1));
    g_frag1[((size_t)(h * 128 + jt) * 4 + tq) * 32 + ff] =
        make_float4(__uint_as_float(bh0), __uint_as_float(bh1),
                    __uint_as_float(bl0), __uint_as_float(bl1));
}

// ---------------- layer1 aggregation: bf16 m16n8k16 ----------------
__global__ __launch_bounds__(256, 4) void agg1_mma_kernel() {
    __shared__ __align__(16) float4 S4[2][2][4][34];
    __shared__ __align__(16) float4 ebd_s[2][32];
    int h = blockIdx.x >> 2;
    int p = blockIdx.x & 3;
    int bi = blockIdx.y * 128;
    int t = threadIdx.x;
    int lane = t & 31, w = t >> 5;
    int g = lane >> 2, tq = lane & 3;
    int iA = bi + w * 16 + g;
    int iB = iA + 8;
    float4 eA = g_eli1t[h * NN + iA];
    float4 eB = g_eli1t[h * NN + iB];
    float acc[4][4] = {};
    float lsA = 0.f, lsB = 0.f;

    int sf = t & 31, stq = (t >> 5) & 3, skt = t >> 7;
    const float4* fb = g_frag1 + (size_t)h * 128 * 4 * 32;
    int jstart = p * (NN / JS1);   // 512 j
    const int NC = (NN / JS1) / 32;  // 16

#define STAGE1(b, j0) do { \
        int jt0 = (j0) >> 4; \
        cpa16((u32)__cvta_generic_to_shared(&S4[b][skt][stq][sf]), \
              fb + ((size_t)(jt0 + skt) * 4 + stq) * 32 + sf); \
        if (t < 32) cpa16((u32)__cvta_generic_to_shared(&ebd_s[b][t]), g_ebd1t + h * NN + (j0) + t); \
    } while (0)

    STAGE1(0, jstart);
    CP_COMMIT;
    for (int c = 0; c < NC; c++) {
        int b = c & 1;
        if (c + 1 < NC) {
            STAGE1(b ^ 1, jstart + (c + 1) * 32);
            CP_COMMIT;
            CP_WAIT1;
        } else {
            CP_WAIT0;
        }
        __syncthreads();
        int j0 = jstart + c * 32;
        unsigned wordA = g_bits[(size_t)iA * NWORDS + (j0 >> 5)];
        unsigned wordB = g_bits[(size_t)iB * NWORDS + (j0 >> 5)];
#pragma unroll
        for (int kt = 0; kt < 2; kt++) {
            int jb = kt * 16 + 2 * tq;
            float4 e1 = ebd_s[b][jb];
            float4 e2 = ebd_s[b][jb + 1];
            float4 e3 = ebd_s[b][jb + 8];
            float4 e4 = ebd_s[b][jb + 9];
            float wA1 = (e1.x > eA.x) ? eA.y * e1.y : eA.z * e1.z;
            float wA2 = (e2.x > eA.x) ? eA.y * e2.y : eA.z * e2.z;
            float wA3 = (e3.x > eA.x) ? eA.y * e3.y : eA.z * e3.z;
            float wA4 = (e4.x > eA.x) ? eA.y * e4.y : eA.z * e4.z;
            float wB1 = (e1.x > eB.x) ? eB.y * e1.y : eB.z * e1.z;
            float wB2 = (e2.x > eB.x) ? eB.y * e2.y : eB.z * e2.z;
            float wB3 = (e3.x > eB.x) ? eB.y * e3.y : eB.z * e3.z;
            float wB4 = (e4.x > eB.x) ? eB.y * e4.y : eB.z * e4.z;
            wA1 = ((wordA >> jb) & 1u) ? wA1 : 0.f;
            wA2 = ((wordA >> (jb + 1)) & 1u) ? wA2 : 0.f;
            wA3 = ((wordA >> (jb + 8)) & 1u) ? wA3 : 0.f;
            wA4 = ((wordA >> (jb + 9)) & 1u) ? wA4 : 0.f;
            wB1 = ((wordB >> jb) & 1u) ? wB1 : 0.f;
            wB2 = ((wordB >> (jb + 1)) & 1u) ? wB2 : 0.f;
            wB3 = ((wordB >> (jb + 8)) & 1u) ? wB3 : 0.f;
            wB4 = ((wordB >> (jb + 9)) & 1u) ? wB4 : 0.f;
            lsA += (wA1 + wA2) + (wA3 + wA4);
            lsB += (wB1 + wB2) + (wB3 + wB4);
            u32 ah[4], al4[4];
            ah[0] = packbf(wA1, wA2); ah[1] = packbf(wB1, wB2);
            ah[2] = packbf(wA3, wA4); ah[3] = packbf(wB3, wB4);
            al4[0] = packbf(wA1 - bf_lo(ah[0]), wA2 - bf_hi(ah[0]));
            al4[1] = packbf(wB1 - bf_lo(ah[1]), wB2 - bf_hi(ah[1]));
            al4[2] = packbf(wA3 - bf_lo(ah[2]), wA4 - bf_hi(ah[2]));
            al4[3] = packbf(wB3 - bf_lo(ah[3]), wB4 - bf_hi(ah[3]));
#pragma unroll
            for (int nt = 0; nt < 4; nt++) {
                float4 bfr = S4[b][kt][tq][nt * 8 + g];
                u32 bh0 = __float_as_uint(bfr.x), bh1 = __float_as_uint(bfr.y);
                u32 bl0 = __float_as_uint(bfr.z), bl1 = __float_as_uint(bfr.w);
                mma16(acc[nt], ah, bh0, bh1);
                mma16(acc[nt], ah, bl0, bl1);
                mma16(acc[nt], al4, bh0, bh1);
            }
        }
        __syncthreads();
    }
    lsA += __shfl_xor_sync(0xffffffffu, lsA, 1);
    lsA += __shfl_xor_sync(0xffffffffu, lsA, 2);
    lsB += __shfl_xor_sync(0xffffffffu, lsB, 1);
    lsB += __shfl_xor_sync(0xffffffffu, lsB, 2);
    size_t rbase = (size_t)p * NN;
    if (tq == 0) {
        g_d1[(rbase + iA) * H1 + h] = lsA;
        g_d1[(rbase + iB) * H1 + h] = lsB;
    }
#pragma unroll
    for (int nt = 0; nt < 4; nt++) {
        int f = h * 32 + nt * 8 + tq * 2;
        *(float2*)(g_n1 + (rbase + iA) * HID + f) = make_float2(acc[nt][0], acc[nt][1]);
        *(float2*)(g_n1 + (rbase + iB) * HID + f) = make_float2(acc[nt][2], acc[nt][3]);
    }
}

// ---------------- reduce1f: partial reduce + divide + ELU + bf16 A-frag emit ----------------
__global__ __launch_bounds__(256) void reduce1f_kernel() {
    __shared__ float v_s[16][132];
    int jt = blockIdx.x;        // 128
    int fh = blockIdx.y;        // 2
    int base = jt * 16;
    int t = threadIdx.x;        // 256
    int f = t & 127, nh = t >> 7;
    int gf = fh * 128 + f;
    int h = gf >> 5;
#pragma unroll
    for (int s8 = 0; s8 < 8; s8++) {
        int node = nh * 8 + s8;
        float num = 0.f, den = 0.f;
#pragma unroll
        for (int p = 0; p < JS1; p++) {
            num += g_n1[((size_t)p * NN + base + node) * HID + gf];
            den += g_d1[(p * NN + base + node) * H1 + h];
        }
        float o = num / den;
        v_s[node][f] = o > 0.f ? o : expm1f(o);
    }
    __syncthreads();
    int lane = t & 31, ktl = t >> 5;
    int kt = fh * 8 + ktl;
    int g = lane >> 2, tq = lane & 3;
    int c = ktl * 16 + 2 * tq;
    float p0a = v_s[g][c],     p0b = v_s[g][c + 1];
    float p1a = v_s[g + 8][c], p1b = v_s[g + 8][c + 1];
    float p2a = v_s[g][c + 8],     p2b = v_s[g][c + 9];
    float p3a = v_s[g + 8][c + 8], p3b = v_s[g + 8][c + 9];
    u32 a0 = packbf(p0a, p0b), a1 = packbf(p1a, p1b);
    u32 a2 = packbf(p2a, p2b), a3 = packbf(p3a, p3b);
    size_t widx = ((size_t)jt * 16 + kt) * 32 + lane;
    g_h1Ah[widx] = make_float4(__uint_as_float(a0), __uint_as_float(a1),
                               __uint_as_float(a2), __uint_as_float(a3));
    u32 l0 = packbf(p0a - bf_lo(a0), p0b - bf_hi(a0));
    u32 l1 = packbf(p1a - bf_lo(a1), p1b - bf_hi(a1));
    u32 l2 = packbf(p2a - bf_lo(a2), p2b - bf_hi(a2));
    u32 l3 = packbf(p3a - bf_lo(a3), p3b - bf_hi(a3));
    g_h1Al[widx] = make_float4(__uint_as_float(l0), __uint_as_float(l1),
                               __uint_as_float(l2), __uint_as_float(l3));
}

// ---------------- gemm2 bf16 tensor: 64i x 64n per block, K-split 4 ----------------
__global__ __launch_bounds__(256) void gemm2_mma_kernel() {
    __shared__ __align__(16) float4 Ah_s[2][4][2][32];
    __shared__ __align__(16) float4 Al_s[2][4][2][32];
    __shared__ __align__(16) float4 Bb_s[2][2][8][32];
    int z = blockIdx.z;
    int bi_t = blockIdx.y * 4;
    int bn_t = blockIdx.x * 8;
    int t = threadIdx.x;
    int lane = t & 31, w = t >> 5;
    int itw = w >> 1, nh = w & 1;
    float acc[4][4] = {};
    int ktz = z * 4;

#define GM2_STAGE(b, ch) do { \
        int kt0 = ktz + (ch) * 2; \
        { int e = t; int ln = e & 31, kk = (e >> 5) & 1, it = e >> 6; \
          size_t gi = ((size_t)(bi_t + it) * 16 + kt0 + kk) * 32 + ln; \
          cpa16((u32)__cvta_generic_to_shared(&Ah_s[b][it][kk][ln]), g_h1Ah + gi); \
          cpa16((u32)__cvta_generic_to_shared(&Al_s[b][it][kk][ln]), g_h1Al + gi); } \
        _Pragma("unroll") \
        for (int q = 0; q < 2; q++) { int e = t + q * 256; \
          int ln = e & 31, nt = (e >> 5) & 7, kk = e >> 8; \
          size_t gb = ((size_t)(kt0 + kk) * 16 + bn_t + nt) * 32 + ln; \
          cpa16((u32)__cvta_generic_to_shared(&Bb_s[b][kk][nt][ln]), g_w2B + gb); } \
    } while (0)

    GM2_STAGE(0, 0);
    CP_COMMIT;
    for (int ch = 0; ch < 2; ch++) {
        int b = ch & 1;
        if (ch + 1 < 2) {
            GM2_STAGE(b ^ 1, ch + 1);
            CP_COMMIT;
            CP_WAIT1;
        } else {
            CP_WAIT0;
        }
        __syncthreads();
#pragma unroll
        for (int kt = 0; kt < 2; kt++) {
            float4 a4h = Ah_s[b][itw][kt][lane];
            float4 a4l = Al_s[b][itw][kt][lane];
            u32 ah[4] = {__float_as_uint(a4h.x), __float_as_uint(a4h.y),
                         __float_as_uint(a4h.z), __float_as_uint(a4h.w)};
            u32 alr[4] = {__float_as_uint(a4l.x), __float_as_uint(a4l.y),
                          __float_as_uint(a4l.z), __float_as_uint(a4l.w)};
#pragma unroll
            for (int n4 = 0; n4 < 4; n4++) {
                float4 bb = Bb_s[b][kt][nh * 4 + n4][lane];
                u32 bh0 = __float_as_uint(bb.x), bh1 = __float_as_uint(bb.y);
                u32 bl0 = __float_as_uint(bb.z), bl1 = __float_as_uint(bb.w);
                mma16(acc[n4], ah, bh0, bh1);
                mma16(acc[n4], ah, bl0, bl1);
                mma16(acc[n4], alr, bh0, bh1);
            }
        }
        __syncthreads();
    }
    int g = lane >> 2, tq = lane & 3;
    int r0 = blockIdx.y * 64 + itw * 16 + g;
    float* Cz = g_gp2 + (size_t)z * NN * OUT_F;
#pragma unroll
    for (int n4 = 0; n4 < 4; n4++) {
        int c = blockIdx.x * 64 + (nh * 4 + n4) * 8 + tq * 2;
        *(float2*)(Cz + (size_t)r0 * OUT_F + c) = make_float2(acc[n4][0], acc[n4][1]);
        *(float2*)(Cz + (size_t)(r0 + 8) * OUT_F + c) = make_float2(acc[n4][2], acc[n4][3]);
    }
}

// ---------------- elr2f: fused K-partial sum + el/er + bf16 fragment emit ----------------
__global__ __launch_bounds__(256) void elr2f_kernel(const float* __restrict__ al,
                                                    const float* __restrict__ ar) {
    __shared__ float v_s[16][128];
    __shared__ float pel[16][4], per[16][4];
    int jt = blockIdx.x;             // 128 blocks
    int base = jt * 16;
    int t = threadIdx.x;
    int f = t & 127, th = t >> 7;
    int wq = (t >> 5) & 3, lane = t & 31;

    float v[8];
#pragma unroll
    for (int s = 0; s < 8; s++) {
        int node = 2 * s + th;
        float x = 0.f;
#pragma unroll
        for (int z = 0; z < KS2G; z++)
            x += g_gp2[((size_t)z * NN + base + node) * OUT_F + f];
        v[s] = x;
        v_s[node][f] = x;
    }
    float alv = al[f], arv = ar[f];
#pragma unroll
    for (int s = 0; s < 8; s++) {
        float pl = v[s] * alv, pr = v[s] * arv;
#pragma unroll
        for (int o = 16; o; o >>= 1) {
            pl += __shfl_down_sync(0xffffffffu, pl, o);
            pr += __shfl_down_sync(0xffffffffu, pr, o);
        }
        if (lane == 0) { pel[2 * s + th][wq] = pl; per[2 * s + th][wq] = pr; }
    }
    __syncthreads();
    if (t < 16) {
        float el = pel[t][0] + pel[t][1] + pel[t][2] + pel[t][3];
        float er = per[t][0] + per[t][1] + per[t][2] + per[t][3];
        g_eli2[base + t] = make_float4(-el, __expf(el), __expf(0.2f * el), 0.f);
        g_ebd2[base + t] = make_float4(er, __expf(er), __expf(0.2f * er), 0.f);
    }
#pragma unroll
    for (int q = 0; q < 2; q++) {
        int widx = t + q * 256;
        int ff = widx & 127, tq = widx >> 7;
        float v0 = v_s[2 * tq][ff];
        float v1 = v_s[2 * tq + 1][ff];
        float v2 = v_s[2 * tq + 8][ff];
        float v3 = v_s[2 * tq + 9][ff];
        u32 bh0 = packbf(v0, v1), bh1 = packbf(v2, v3);
        u32 bl0 = packbf(v0 - bf_lo(bh0), v1 - bf_hi(bh0));
        u32 bl1 = packbf(v2 - bf_lo(bh1), v3 - bf_hi(bh1));
        g_frag2[((size_t)jt * 4 + tq) * 128 + ff] =
            make_float4(__uint_as_float(bh0), __uint_as_float(bh1),
                        __uint_as_float(bl0), __uint_as_float(bl1));
    }
}

// ---------------- layer2 aggregation: bf16 m16n8k16, 64-row tiles ----------------
__global__ __launch_bounds__(256, 4) void agg2_mma_kernel() {
    __shared__ __align__(16) float4 S4[2][4][130];
    __shared__ __align__(16) float4 ebd_s[2][16];
    int p = blockIdx.x;          // 0..7
    int bi = blockIdx.y * 64;
    int t = threadIdx.x;
    int lane = t & 31, w = t >> 5;
    int g = lane >> 2, tq = lane & 3;
    int it = w >> 1, nth = w & 1;
    int iA = bi + it * 16 + g;
    int iB = iA + 8;
    float4 eA = g_eli2[iA];
    float4 eB = g_eli2[iB];
    float acc[8][4] = {};
    float lsA = 0.f, lsB = 0.f;

    int jstart = p * (NN / JS2);     // 256 j
    const int NC = (NN / JS2) / 16;  // 16

#define STAGE2(b, j0) do { \
        int jt0 = (j0) >> 4; \
        _Pragma("unroll") \
        for (int e = t; e < 512; e += 256) { \
            int sq = e >> 7, ff = e & 127; \
            cpa16((u32)__cvta_generic_to_shared(&S4[b][sq][ff]), \
                  g_frag2 + ((size_t)jt0 * 4 + sq) * 128 + ff); \
        } \
        if (t < 16) cpa16((u32)__cvta_generic_to_shared(&ebd_s[b][t]), g_ebd2 + (j0) + t); \
    } while (0)

    STAGE2(0, jstart);
    CP_COMMIT;
    for (int c = 0; c < NC; c++) {
        int b = c & 1;
        if (c + 1 < NC) {
            STAGE2(b ^ 1, jstart + (c + 1) * 16);
            CP_COMMIT;
            CP_WAIT1;
        } else {
            CP_WAIT0;
        }
        __syncthreads();
        int j0 = jstart + c * 16;
        unsigned wordA = g_bits[(size_t)iA * NWORDS + (j0 >> 5)] >> (j0 & 31);
        unsigned wordB = g_bits[(size_t)iB * NWORDS + (j0 >> 5)] >> (j0 & 31);
        int jb = 2 * tq;
        float4 e1 = ebd_s[b][jb];
        float4 e2 = ebd_s[b][jb + 1];
        float4 e3 = ebd_s[b][jb + 8];
        float4 e4 = ebd_s[b][jb + 9];
        float wA1 = (e1.x > eA.x) ? eA.y * e1.y : eA.z * e1.z;
        float wA2 = (e2.x > eA.x) ? eA.y * e2.y : eA.z * e2.z;
        float wA3 = (e3.x > eA.x) ? eA.y * e3.y : eA.z * e3.z;
        float wA4 = (e4.x > eA.x) ? eA.y * e4.y : eA.z * e4.z;
        float wB1 = (e1.x > eB.x) ? eB.y * e1.y : eB.z * e1.z;
        float wB2 = (e2.x > eB.x) ? eB.y * e2.y : eB.z * e2.z;
        float wB3 = (e3.x > eB.x) ? eB.y * e3.y : eB.z * e3.z;
        float wB4 = (e4.x > eB.x) ? eB.y * e4.y : eB.z * e4.z;
        wA1 = ((wordA >> jb) & 1u) ? wA1 : 0.f;
        wA2 = ((wordA >> (jb + 1)) & 1u) ? wA2 : 0.f;
        wA3 = ((wordA >> (jb + 8)) & 1u) ? wA3 : 0.f;
        wA4 = ((wordA >> (jb + 9)) & 1u) ? wA4 : 0.f;
        wB1 = ((wordB >> jb) & 1u) ? wB1 : 0.f;
        wB2 = ((wordB >> (jb + 1)) & 1u) ? wB2 : 0.f;
        wB3 = ((wordB >> (jb + 8)) & 1u) ? wB3 : 0.f;
        wB4 = ((wordB >> (jb + 9)) & 1u) ? wB4 : 0.f;
        lsA += (wA1 + wA2) + (wA3 + wA4);
        lsB += (wB1 + wB2) + (wB3 + wB4);
        u32 ah[4], al4[4];
        ah[0] = packbf(wA1, wA2); ah[1] = packbf(wB1, wB2);
        ah[2] = packbf(wA3, wA4); ah[3] = packbf(wB3, wB4);
        al4[0] = packbf(wA1 - bf_lo(ah[0]), wA2 - bf_hi(ah[0]));
        al4[1] = packbf(wB1 - bf_lo(ah[1]), wB2 - bf_hi(ah[1]));
        al4[2] = packbf(wA3 - bf_lo(ah[2]), wA4 - bf_hi(ah[2]));
        al4[3] = packbf(wB3 - bf_lo(ah[3]), wB4 - bf_hi(ah[3]));
#pragma unroll
        for (int nt = 0; nt < 8; nt++) {
            float4 bfr = S4[b][tq][(nth * 8 + nt) * 8 + g];
            u32 bh0 = __float_as_uint(bfr.x), bh1 = __float_as_uint(bfr.y);
            u32 bl0 = __float_as_uint(bfr.z), bl1 = __float_as_uint(bfr.w);
            mma16(acc[nt], ah, bh0, bh1);
            mma16(acc[nt], ah, bl0, bl1);
            mma16(acc[nt], al4, bh0, bh1);
        }
        __syncthreads();
    }
    lsA += __shfl_xor_sync(0xffffffffu, lsA, 1);
    lsA += __shfl_xor_sync(0xffffffffu, lsA, 2);
    lsB += __shfl_xor_sync(0xffffffffu, lsB, 1);
    lsB += __shfl_xor_sync(0xffffffffu, lsB, 2);
    if (tq == 0 && nth == 0) {
        g_psum[p * NN + iA] = lsA;
        g_psum[p * NN + iB] = lsB;
    }
    float* pb = g_part + (size_t)p * NN * OUT_F;
#pragma unroll
    for (int nt = 0; nt < 8; nt++) {
        int f = (nth * 8 + nt) * 8 + tq * 2;
        *(float2*)(pb + (size_t)iA * OUT_F + f) = make_float2(acc[nt][0], acc[nt][1]);
        *(float2*)(pb + (size_t)iB * OUT_F + f) = make_float2(acc[nt][2], acc[nt][3]);
    }
}

// ---------------- final reduce + divide ----------------
__global__ void reduce2_kernel(float* __restrict__ out) {
    int i = blockIdx.x;
    int f = threadIdx.x;  // 128
    float num = 0.f, den = 0.f;
#pragma unroll
    for (int p = 0; p < JS2; p++) {
        num += g_part[(size_t)p * NN * OUT_F + (size_t)i * OUT_F + f];
        den += g_psum[p * NN + i];
    }
    out[i * OUT_F + f] = num / den;
}

// ---------------- launch ----------------
extern "C" void kernel_launch(void* const* d_in, const int* in_sizes, int n_in,
                              void* d_out, int out_size) {
    const float* x    = (const float*)d_in[0];
    const float* W1   = (const float*)d_in[1];
    const float* a1_l = (const float*)d_in[2];
    const float* a1_r = (const float*)d_in[3];
    const float* W2   = (const float*)d_in[4];
    const float* a2_l = (const float*)d_in[5];
    const float* a2_r = (const float*)d_in[6];
    const int*   adj  = (const int*)d_in[7];
    float* out = (float*)d_out;

    prep0_kernel<<<NN + 672, 256>>>(adj, x, W1, W2);
    gemm1_mma_kernel<<<dim3(4, 32, KS1G), 256>>>();
    elr1f_kernel<<<dim3(128, 4), 256>>>(a1_l, a1_r);
    agg1_mma_kernel<<<dim3(H1 * JS1, NN / 128), 256>>>();
    reduce1f_kernel<<<dim3(128, 2), 256>>>();
    gemm2_mma_kernel<<<dim3(2, 32, KS2G), 256>>>();
    elr2f_kernel<<<128, 256>>>(a2_l, a2_r);
    agg2_mma_kernel<<<dim3(JS2, NN / 64), 256>>>();
    reduce2_kernel<<<NN, 128>>>(out);
}

// round 14
// speedup vs baseline: 1.1068x; 1.1068x over previous
#include <cuda_runtime.h>

#define NN     2048
#define IN_F   512
#define HID    256
#define OUT_F  128
#define H1     8
#define NWORDS 64   // NN/32
#define JS1    4    // agg1 j-split
#define JS2    8    // agg2 j-split
#define KS1G   2    // gemm1 K-split
#define KS2G   4    // gemm2 K-split

typedef unsigned u32;

// pack {lo, hi} floats into bf16x2 (element0 = lo)
__device__ __forceinline__ u32 packbf(float lo, float hi) {
    u32 d; asm("cvt.rn.bf16x2.f32 %0, %1, %2;" : "=r"(d) : "f"(hi), "f"(lo)); return d;
}
__device__ __forceinline__ float bf_lo(u32 p) { return __uint_as_float(p << 16); }
__device__ __forceinline__ float bf_hi(u32 p) { return __uint_as_float(p & 0xffff0000u); }

__device__ __forceinline__ void mma16(float* d, const u32* a, u32 b0, u32 b1) {
    asm volatile(
        "mma.sync.aligned.m16n8k16.row.col.f32.bf16.bf16.f32 "
        "{%0,%1,%2,%3}, {%4,%5,%6,%7}, {%8,%9}, {%0,%1,%2,%3};"
        : "+f"(d[0]), "+f"(d[1]), "+f"(d[2]), "+f"(d[3])
        : "r"(a[0]), "r"(a[1]), "r"(a[2]), "r"(a[3]), "r"(b0), "r"(b1));
}
__device__ __forceinline__ void cpa16(u32 s, const void* g) {
    asm volatile("cp.async.ca.shared.global [%0], [%1], 16;" :: "r"(s), "l"(g));
}
#define CP_COMMIT asm volatile("cp.async.commit_group;")
#define CP_WAIT1  asm volatile("cp.async.wait_group 1;")
#define CP_WAIT0  asm volatile("cp.async.wait_group 0;")

// ---------------- scratch ----------------
__device__ __align__(16) float4 g_xAh[128 * 32 * 32];   // x A-frag hi (2MB)
__device__ __align__(16) float4 g_xAl[128 * 32 * 32];
__device__ __align__(16) float4 g_w1B[32 * 32 * 32];    // W1 B-frags
__device__ __align__(16) float4 g_w2B[16 * 16 * 32];    // W2 B-frags
__device__ __align__(16) float  g_gp1[KS1G * NN * HID];
__device__ __align__(16) float2 g_eli1t[H1 * NN];   // [h][i] {exp(el), exp(0.2el)}
__device__ __align__(16) float2 g_ebd1t[H1 * NN];   // [h][j] {exp(er), exp(0.2er)}
__device__ __align__(16) float4 g_frag1[H1 * 128 * 4 * 32];   // agg1 bf16 B-frags (2MB)
__device__ unsigned g_bits[NN * NWORDS];
__device__ __align__(16) float  g_n1[JS1 * NN * HID];
__device__ float  g_d1[JS1 * NN * H1];
__device__ __align__(16) float4 g_h1Ah[128 * 16 * 32];  // h1 A-frags hi (1MB)
__device__ __align__(16) float4 g_h1Al[128 * 16 * 32];
__device__ __align__(16) float  g_gp2[KS2G * NN * OUT_F];
__device__ __align__(16) float2 g_eli2[NN];
__device__ __align__(16) float2 g_ebd2[NN];
__device__ __align__(16) float4 g_frag2[128 * 4 * 128];       // agg2 bf16 B-frags (1MB)
__device__ __align__(16) float  g_part[JS2 * NN * OUT_F];
__device__ float  g_psum[JS2 * NN];

// ---------------- prep0: pack adjacency (blocks < NN) + input fragments ----------------
__global__ void prep0_kernel(const int* __restrict__ adj, const float* __restrict__ x,
                             const float* __restrict__ W1, const float* __restrict__ W2) {
    int t = threadIdx.x;  // 256
    if (blockIdx.x < NN) {
        int i = blockIdx.x;
        const int* row = adj + (size_t)i * NN;
#pragma unroll
        for (int k = 0; k < 8; k++) {
            int j = k * 256 + t;
            unsigned b = __ballot_sync(0xffffffffu, row[j] != 0);
            if ((t & 31) == 0) g_bits[i * NWORDS + (j >> 5)] = b;
        }
        return;
    }
    int idx = (blockIdx.x - NN) * 256 + t;   // < 172032
    if (idx < 131072) {
        int lane = idx & 31, kt = (idx >> 5) & 31, it = idx >> 10;
        int g = lane >> 2, tq = lane & 3;
        int r = it * 16 + g, c = kt * 16 + 2 * tq;
        const float* xr = x + (size_t)r * IN_F + c;
        float2 p0 = *(const float2*)xr;
        float2 p1 = *(const float2*)(xr + 8 * IN_F);
        float2 p2 = *(const float2*)(xr + 8);
        float2 p3 = *(const float2*)(xr + 8 * IN_F + 8);
        u32 a0 = packbf(p0.x, p0.y), a1 = packbf(p1.x, p1.y);
        u32 a2 = packbf(p2.x, p2.y), a3 = packbf(p3.x, p3.y);
        g_xAh[idx] = make_float4(__uint_as_float(a0), __uint_as_float(a1),
                                 __uint_as_float(a2), __uint_as_float(a3));
        u32 l0 = packbf(p0.x - bf_lo(a0), p0.y - bf_hi(a0));
        u32 l1 = packbf(p1.x - bf_lo(a1), p1.y - bf_hi(a1));
        u32 l2 = packbf(p2.x - bf_lo(a2), p2.y - bf_hi(a2));
        u32 l3 = packbf(p3.x - bf_lo(a3), p3.y - bf_hi(a3));
        g_xAl[idx] = make_float4(__uint_as_float(l0), __uint_as_float(l1),
                                 __uint_as_float(l2), __uint_as_float(l3));
    } else if (idx < 163840) {
        int e = idx - 131072;                   // < 32768
        int lane = e & 31, nt = (e >> 5) & 31, kt = e >> 10;
        int g = lane >> 2, tq = lane & 3;
        int n = nt * 8 + g, k0 = kt * 16 + 2 * tq;
        float b0a = W1[(size_t)k0 * HID + n];
        float b0b = W1[(size_t)(k0 + 1) * HID + n];
        float b1a = W1[(size_t)(k0 + 8) * HID + n];
        float b1b = W1[(size_t)(k0 + 9) * HID + n];
        u32 bh0 = packbf(b0a, b0b), bh1 = packbf(b1a, b1b);
        u32 bl0 = packbf(b0a - bf_lo(bh0), b0b - bf_hi(bh0));
        u32 bl1 = packbf(b1a - bf_lo(bh1), b1b - bf_hi(bh1));
        g_w1B[e] = make_float4(__uint_as_float(bh0), __uint_as_float(bh1),
                               __uint_as_float(bl0), __uint_as_float(bl1));
    } else {
        int e = idx - 163840;                   // < 8192
        int lane = e & 31, nt = (e >> 5) & 15, kt = e >> 9;
        int g = lane >> 2, tq = lane & 3;
        int n = nt * 8 + g, k0 = kt * 16 + 2 * tq;
        float b0a = W2[(size_t)k0 * OUT_F + n];
        float b0b = W2[(size_t)(k0 + 1) * OUT_F + n];
        float b1a = W2[(size_t)(k0 + 8) * OUT_F + n];
        float b1b = W2[(size_t)(k0 + 9) * OUT_F + n];
        u32 bh0 = packbf(b0a, b0b), bh1 = packbf(b1a, b1b);
        u32 bl0 = packbf(b0a - bf_lo(bh0), b0b - bf_hi(bh0));
        u32 bl1 = packbf(b1a - bf_lo(bh1), b1b - bf_hi(bh1));
        g_w2B[e] = make_float4(__uint_as_float(bh0), __uint_as_float(bh1),
                               __uint_as_float(bl0), __uint_as_float(bl1));
    }
}

// ---------------- gemm1 bf16 tensor: 64i x 64n per block, K-split 2 ----------------
__global__ __launch_bounds__(256) void gemm1_mma_kernel() {
    __shared__ __align__(16) float4 Ah_s[2][4][2][32];
    __shared__ __align__(16) float4 Al_s[2][4][2][32];
    __shared__ __align__(16) float4 Bb_s[2][2][8][32];
    int z = blockIdx.z;
    int bi_t = blockIdx.y * 4;
    int bn_t = blockIdx.x * 8;
    int t = threadIdx.x;
    int lane = t & 31, w = t >> 5;
    int itw = w >> 1, nh = w & 1;
    float acc[4][4] = {};
    int ktz = z * 16;

#define GM_STAGE(b, ch) do { \
        int kt0 = ktz + (ch) * 2; \
        { int e = t; int ln = e & 31, kk = (e >> 5) & 1, it = e >> 6; \
          size_t gi = ((size_t)(bi_t + it) * 32 + kt0 + kk) * 32 + ln; \
          cpa16((u32)__cvta_generic_to_shared(&Ah_s[b][it][kk][ln]), g_xAh + gi); \
          cpa16((u32)__cvta_generic_to_shared(&Al_s[b][it][kk][ln]), g_xAl + gi); } \
        _Pragma("unroll") \
        for (int q = 0; q < 2; q++) { int e = t + q * 256; \
          int ln = e & 31, nt = (e >> 5) & 7, kk = e >> 8; \
          size_t gb = ((size_t)(kt0 + kk) * 32 + bn_t + nt) * 32 + ln; \
          cpa16((u32)__cvta_generic_to_shared(&Bb_s[b][kk][nt][ln]), g_w1B + gb); } \
    } while (0)

    GM_STAGE(0, 0);
    CP_COMMIT;
    for (int ch = 0; ch < 8; ch++) {
        int b = ch & 1;
        if (ch + 1 < 8) {
            GM_STAGE(b ^ 1, ch + 1);
            CP_COMMIT;
            CP_WAIT1;
        } else {
            CP_WAIT0;
        }
        __syncthreads();
#pragma unroll
        for (int kt = 0; kt < 2; kt++) {
            float4 a4h = Ah_s[b][itw][kt][lane];
            float4 a4l = Al_s[b][itw][kt][lane];
            u32 ah[4] = {__float_as_uint(a4h.x), __float_as_uint(a4h.y),
                         __float_as_uint(a4h.z), __float_as_uint(a4h.w)};
            u32 alr[4] = {__float_as_uint(a4l.x), __float_as_uint(a4l.y),
                          __float_as_uint(a4l.z), __float_as_uint(a4l.w)};
#pragma unroll
            for (int n4 = 0; n4 < 4; n4++) {
                float4 bb = Bb_s[b][kt][nh * 4 + n4][lane];
                u32 bh0 = __float_as_uint(bb.x), bh1 = __float_as_uint(bb.y);
                u32 bl0 = __float_as_uint(bb.z), bl1 = __float_as_uint(bb.w);
                mma16(acc[n4], ah, bh0, bh1);
                mma16(acc[n4], ah, bl0, bl1);
                mma16(acc[n4], alr, bh0, bh1);
            }
        }
        __syncthreads();
    }
    int g = lane >> 2, tq = lane & 3;
    int r0 = blockIdx.y * 64 + itw * 16 + g;
    float* Cz = g_gp1 + (size_t)z * NN * HID;
#pragma unroll
    for (int n4 = 0; n4 < 4; n4++) {
        int c = blockIdx.x * 64 + (nh * 4 + n4) * 8 + tq * 2;
        *(float2*)(Cz + (size_t)r0 * HID + c) = make_float2(acc[n4][0], acc[n4][1]);
        *(float2*)(Cz + (size_t)(r0 + 8) * HID + c) = make_float2(acc[n4][2], acc[n4][3]);
    }
}

// ---------------- elr1f: per-(jt, head-pair) fused partial-sum + el/er + frag emit ----------------
__global__ __launch_bounds__(256) void elr1f_kernel(const float* __restrict__ al,
                                                    const float* __restrict__ ar) {
    __shared__ float v_s[2][16][32];
    __shared__ float elb[2][16], erb[2][16];
    int jt = blockIdx.x;       // 128
    int base = jt * 16;
    int t = threadIdx.x;       // 256
    int hl = t >> 7;           // local head 0/1
    int tt = t & 127;
    int h = blockIdx.y * 2 + hl;  // 0..7
    int f = tt & 31, wr = tt >> 5;
    float alv = al[f], arv = ar[f];
#pragma unroll
    for (int s4 = 0; s4 < 4; s4++) {
        int node = wr * 4 + s4;
        float x = 0.f;
#pragma unroll
        for (int z = 0; z < KS1G; z++)
            x += g_gp1[((size_t)z * NN + base + node) * HID + h * 32 + f];
        v_s[hl][node][f] = x;
        float pl = x * alv, pr = x * arv;
#pragma unroll
        for (int o = 16; o; o >>= 1) {
            pl += __shfl_down_sync(0xffffffffu, pl, o);
            pr += __shfl_down_sync(0xffffffffu, pr, o);
        }
        if (f == 0) { elb[hl][node] = pl; erb[hl][node] = pr; }
    }
    __syncthreads();
    if (t < 32) {
        int hl2 = t >> 4, s = t & 15;
        int hh = blockIdx.y * 2 + hl2;
        float el = elb[hl2][s], er = erb[hl2][s];
        g_eli1t[hh * NN + base + s] = make_float2(__expf(el), __expf(0.2f * el));
        g_ebd1t[hh * NN + base + s] = make_float2(__expf(er), __expf(0.2f * er));
    }
    int tq = tt >> 5, ff = tt & 31;
    float v0 = v_s[hl][2 * tq][ff];
    float v1 = v_s[hl][2 * tq + 1][ff];
    float v2 = v_s[hl][2 * tq + 8][ff];
    float v3 = v_s[hl][2 * tq + 9][ff];
    u32 bh0 = packbf(v0, v1), bh1 = packbf(v2, v3);
    u32 bl0 = packbf(v0 - bf_lo(bh0), v1 - bf_hi(bh0));
    u32 bl1 = packbf(v2 - bf_lo(bh1), v3 - bf_hi(bh1));
    g_frag1[((size_t)(h * 128 + jt) * 4 + tq) * 32 + ff] =
        make_float4(__uint_as_float(bh0), __uint_as_float(bh1),
                    __uint_as_float(bl0), __uint_as_float(bl1));
}

// ---------------- layer1 aggregation: bf16 m16n8k16, max-trick weights, 3-buf 1-sync ----------------
__global__ __launch_bounds__(256, 4) void agg1_mma_kernel() {
    __shared__ __align__(16) float4 S4[3][2][4][34];
    __shared__ __align__(16) float2 ebd_s[3][32];
    int h = blockIdx.x >> 2;
    int p = blockIdx.x & 3;
    int bi = blockIdx.y * 128;
    int t = threadIdx.x;
    int lane = t & 31, w = t >> 5;
    int g = lane >> 2, tq = lane & 3;
    int iA = bi + w * 16 + g;
    int iB = iA + 8;
    float2 eA = g_eli1t[h * NN + iA];   // {A, C}
    float2 eB = g_eli1t[h * NN + iB];
    float acc[4][4] = {};
    float lsA = 0.f, lsB = 0.f;

    int sf = t & 31, stq = (t >> 5) & 3, skt = t >> 7;
    const float4* fb = g_frag1 + (size_t)h * 128 * 4 * 32;
    int jstart = p * (NN / JS1);   // 512 j
    const int NC = (NN / JS1) / 32;  // 16

#define STAGE1(bu, j0) do { \
        int jt0 = (j0) >> 4; \
        cpa16((u32)__cvta_generic_to_shared(&S4[bu][skt][stq][sf]), \
              fb + ((size_t)(jt0 + skt) * 4 + stq) * 32 + sf); \
        if (t < 16) cpa16((u32)__cvta_generic_to_shared(&ebd_s[bu][2 * t]), \
                          g_ebd1t + h * NN + (j0) + 2 * t); \
    } while (0)

    STAGE1(0, jstart);
    CP_COMMIT;
    STAGE1(1, jstart + 32);
    CP_COMMIT;
    for (int c = 0; c < NC; c++) {
        int bu = c % 3;
        if (c + 1 < NC) CP_WAIT1; else CP_WAIT0;
        __syncthreads();
        if (c + 2 < NC) {
            STAGE1((c + 2) % 3, jstart + (c + 2) * 32);
            CP_COMMIT;
        }
        int j0 = jstart + c * 32;
        unsigned wordA = g_bits[(size_t)iA * NWORDS + (j0 >> 5)];
        unsigned wordB = g_bits[(size_t)iB * NWORDS + (j0 >> 5)];
#pragma unroll
        for (int kt = 0; kt < 2; kt++) {
            int jb = kt * 16 + 2 * tq;
            float2 e1 = ebd_s[bu][jb];
            float2 e2 = ebd_s[bu][jb + 1];
            float2 e3 = ebd_s[bu][jb + 8];
            float2 e4 = ebd_s[bu][jb + 9];
            float wA1 = fmaxf(eA.x * e1.x, eA.y * e1.y);
            float wA2 = fmaxf(eA.x * e2.x, eA.y * e2.y);
            float wA3 = fmaxf(eA.x * e3.x, eA.y * e3.y);
            float wA4 = fmaxf(eA.x * e4.x, eA.y * e4.y);
            float wB1 = fmaxf(eB.x * e1.x, eB.y * e1.y);
            float wB2 = fmaxf(eB.x * e2.x, eB.y * e2.y);
            float wB3 = fmaxf(eB.x * e3.x, eB.y * e3.y);
            float wB4 = fmaxf(eB.x * e4.x, eB.y * e4.y);
            wA1 = ((wordA >> jb) & 1u) ? wA1 : 0.f;
            wA2 = ((wordA >> (jb + 1)) & 1u) ? wA2 : 0.f;
            wA3 = ((wordA >> (jb + 8)) & 1u) ? wA3 : 0.f;
            wA4 = ((wordA >> (jb + 9)) & 1u) ? wA4 : 0.f;
            wB1 = ((wordB >> jb) & 1u) ? wB1 : 0.f;
            wB2 = ((wordB >> (jb + 1)) & 1u) ? wB2 : 0.f;
            wB3 = ((wordB >> (jb + 8)) & 1u) ? wB3 : 0.f;
            wB4 = ((wordB >> (jb + 9)) & 1u) ? wB4 : 0.f;
            lsA += (wA1 + wA2) + (wA3 + wA4);
            lsB += (wB1 + wB2) + (wB3 + wB4);
            u32 ah[4], al4[4];
            ah[0] = packbf(wA1, wA2); ah[1] = packbf(wB1, wB2);
            ah[2] = packbf(wA3, wA4); ah[3] = packbf(wB3, wB4);
            al4[0] = packbf(wA1 - bf_lo(ah[0]), wA2 - bf_hi(ah[0]));
            al4[1] = packbf(wB1 - bf_lo(ah[1]), wB2 - bf_hi(ah[1]));
            al4[2] = packbf(wA3 - bf_lo(ah[2]), wA4 - bf_hi(ah[2]));
            al4[3] = packbf(wB3 - bf_lo(ah[3]), wB4 - bf_hi(ah[3]));
#pragma unroll
            for (int nt = 0; nt < 4; nt++) {
                float4 bfr = S4[bu][kt][tq][nt * 8 + g];
                u32 bh0 = __float_as_uint(bfr.x), bh1 = __float_as_uint(bfr.y);
                u32 bl0 = __float_as_uint(bfr.z), bl1 = __float_as_uint(bfr.w);
                mma16(acc[nt], ah, bh0, bh1);
                mma16(acc[nt], ah, bl0, bl1);
                mma16(acc[nt], al4, bh0, bh1);
            }
        }
    }
    lsA += __shfl_xor_sync(0xffffffffu, lsA, 1);
    lsA += __shfl_xor_sync(0xffffffffu, lsA, 2);
    lsB += __shfl_xor_sync(0xffffffffu, lsB, 1);
    lsB += __shfl_xor_sync(0xffffffffu, lsB, 2);
    size_t rbase = (size_t)p * NN;
    if (tq == 0) {
        g_d1[(rbase + iA) * H1 + h] = lsA;
        g_d1[(rbase + iB) * H1 + h] = lsB;
    }
#pragma unroll
    for (int nt = 0; nt < 4; nt++) {
        int f = h * 32 + nt * 8 + tq * 2;
        *(float2*)(g_n1 + (rbase + iA) * HID + f) = make_float2(acc[nt][0], acc[nt][1]);
        *(float2*)(g_n1 + (rbase + iB) * HID + f) = make_float2(acc[nt][2], acc[nt][3]);
    }
}

// ---------------- reduce1f: partial reduce + divide + ELU + bf16 A-frag emit ----------------
__global__ __launch_bounds__(256) void reduce1f_kernel() {
    __shared__ float v_s[16][132];
    int jt = blockIdx.x;        // 128
    int fh = blockIdx.y;        // 2
    int base = jt * 16;
    int t = threadIdx.x;        // 256
    int f = t & 127, nh = t >> 7;
    int gf = fh * 128 + f;
    int h = gf >> 5;
#pragma unroll
    for (int s8 = 0; s8 < 8; s8++) {
        int node = nh * 8 + s8;
        float num = 0.f, den = 0.f;
#pragma unroll
        for (int p = 0; p < JS1; p++) {
            num += g_n1[((size_t)p * NN + base + node) * HID + gf];
            den += g_d1[(p * NN + base + node) * H1 + h];
        }
        float o = num / den;
        v_s[node][f] = o > 0.f ? o : expm1f(o);
    }
    __syncthreads();
    int lane = t & 31, ktl = t >> 5;
    int kt = fh * 8 + ktl;
    int g = lane >> 2, tq = lane & 3;
    int c = ktl * 16 + 2 * tq;
    float p0a = v_s[g][c],     p0b = v_s[g][c + 1];
    float p1a = v_s[g + 8][c], p1b = v_s[g + 8][c + 1];
    float p2a = v_s[g][c + 8],     p2b = v_s[g][c + 9];
    float p3a = v_s[g + 8][c + 8], p3b = v_s[g + 8][c + 9];
    u32 a0 = packbf(p0a, p0b), a1 = packbf(p1a, p1b);
    u32 a2 = packbf(p2a, p2b), a3 = packbf(p3a, p3b);
    size_t widx = ((size_t)jt * 16 + kt) * 32 + lane;
    g_h1Ah[widx] = make_float4(__uint_as_float(a0), __uint_as_float(a1),
                               __uint_as_float(a2), __uint_as_float(a3));
    u32 l0 = packbf(p0a - bf_lo(a0), p0b - bf_hi(a0));
    u32 l1 = packbf(p1a - bf_lo(a1), p1b - bf_hi(a1));
    u32 l2 = packbf(p2a - bf_lo(a2), p2b - bf_hi(a2));
    u32 l3 = packbf(p3a - bf_lo(a3), p3b - bf_hi(a3));
    g_h1Al[widx] = make_float4(__uint_as_float(l0), __uint_as_float(l1),
                               __uint_as_float(l2), __uint_as_float(l3));
}

// ---------------- gemm2 bf16 tensor: 64i x 64n per block, K-split 4 ----------------
__global__ __launch_bounds__(256) void gemm2_mma_kernel() {
    __shared__ __align__(16) float4 Ah_s[2][4][2][32];
    __shared__ __align__(16) float4 Al_s[2][4][2][32];
    __shared__ __align__(16) float4 Bb_s[2][2][8][32];
    int z = blockIdx.z;
    int bi_t = blockIdx.y * 4;
    int bn_t = blockIdx.x * 8;
    int t = threadIdx.x;
    int lane = t & 31, w = t >> 5;
    int itw = w >> 1, nh = w & 1;
    float acc[4][4] = {};
    int ktz = z * 4;

#define GM2_STAGE(b, ch) do { \
        int kt0 = ktz + (ch) * 2; \
        { int e = t; int ln = e & 31, kk = (e >> 5) & 1, it = e >> 6; \
          size_t gi = ((size_t)(bi_t + it) * 16 + kt0 + kk) * 32 + ln; \
          cpa16((u32)__cvta_generic_to_shared(&Ah_s[b][it][kk][ln]), g_h1Ah + gi); \
          cpa16((u32)__cvta_generic_to_shared(&Al_s[b][it][kk][ln]), g_h1Al + gi); } \
        _Pragma("unroll") \
        for (int q = 0; q < 2; q++) { int e = t + q * 256; \
          int ln = e & 31, nt = (e >> 5) & 7, kk = e >> 8; \
          size_t gb = ((size_t)(kt0 + kk) * 16 + bn_t + nt) * 32 + ln; \
          cpa16((u32)__cvta_generic_to_shared(&Bb_s[b][kk][nt][ln]), g_w2B + gb); } \
    } while (0)

    GM2_STAGE(0, 0);
    CP_COMMIT;
    for (int ch = 0; ch < 2; ch++) {
        int b = ch & 1;
        if (ch + 1 < 2) {
            GM2_STAGE(b ^ 1, ch + 1);
            CP_COMMIT;
            CP_WAIT1;
        } else {
            CP_WAIT0;
        }
        __syncthreads();
#pragma unroll
        for (int kt = 0; kt < 2; kt++) {
            float4 a4h = Ah_s[b][itw][kt][lane];
            float4 a4l = Al_s[b][itw][kt][lane];
            u32 ah[4] = {__float_as_uint(a4h.x), __float_as_uint(a4h.y),
                         __float_as_uint(a4h.z), __float_as_uint(a4h.w)};
            u32 alr[4] = {__float_as_uint(a4l.x), __float_as_uint(a4l.y),
                          __float_as_uint(a4l.z), __float_as_uint(a4l.w)};
#pragma unroll
            for (int n4 = 0; n4 < 4; n4++) {
                float4 bb = Bb_s[b][kt][nh * 4 + n4][lane];
                u32 bh0 = __float_as_uint(bb.x), bh1 = __float_as_uint(bb.y);
                u32 bl0 = __float_as_uint(bb.z), bl1 = __float_as_uint(bb.w);
                mma16(acc[n4], ah, bh0, bh1);
                mma16(acc[n4], ah, bl0, bl1);
                mma16(acc[n4], alr, bh0, bh1);
            }
        }
        __syncthreads();
    }
    int g = lane >> 2, tq = lane & 3;
    int r0 = blockIdx.y * 64 + itw * 16 + g;
    float* Cz = g_gp2 + (size_t)z * NN * OUT_F;
#pragma unroll
    for (int n4 = 0; n4 < 4; n4++) {
        int c = blockIdx.x * 64 + (nh * 4 + n4) * 8 + tq * 2;
        *(float2*)(Cz + (size_t)r0 * OUT_F + c) = make_float2(acc[n4][0], acc[n4][1]);
        *(float2*)(Cz + (size_t)(r0 + 8) * OUT_F + c) = make_float2(acc[n4][2], acc[n4][3]);
    }
}

// ---------------- elr2f: fused K-partial sum + el/er + bf16 fragment emit ----------------
__global__ __launch_bounds__(256) void elr2f_kernel(const float* __restrict__ al,
                                                    const float* __restrict__ ar) {
    __shared__ float v_s[16][128];
    __shared__ float pel[16][4], per[16][4];
    int jt = blockIdx.x;             // 128 blocks
    int base = jt * 16;
    int t = threadIdx.x;
    int f = t & 127, th = t >> 7;
    int wq = (t >> 5) & 3, lane = t & 31;

    float v[8];
#pragma unroll
    for (int s = 0; s < 8; s++) {
        int node = 2 * s + th;
        float x = 0.f;
#pragma unroll
        for (int z = 0; z < KS2G; z++)
            x += g_gp2[((size_t)z * NN + base + node) * OUT_F + f];
        v[s] = x;
        v_s[node][f] = x;
    }
    float alv = al[f], arv = ar[f];
#pragma unroll
    for (int s = 0; s < 8; s++) {
        float pl = v[s] * alv, pr = v[s] * arv;
#pragma unroll
        for (int o = 16; o; o >>= 1) {
            pl += __shfl_down_sync(0xffffffffu, pl, o);
            pr += __shfl_down_sync(0xffffffffu, pr, o);
        }
        if (lane == 0) { pel[2 * s + th][wq] = pl; per[2 * s + th][wq] = pr; }
    }
    __syncthreads();
    if (t < 16) {
        float el = pel[t][0] + pel[t][1] + pel[t][2] + pel[t][3];
        float er = per[t][0] + per[t][1] + per[t][2] + per[t][3];
        g_eli2[base + t] = make_float2(__expf(el), __expf(0.2f * el));
        g_ebd2[base + t] = make_float2(__expf(er), __expf(0.2f * er));
    }
#pragma unroll
    for (int q = 0; q < 2; q++) {
        int widx = t + q * 256;
        int ff = widx & 127, tq = widx >> 7;
        float v0 = v_s[2 * tq][ff];
        float v1 = v_s[2 * tq + 1][ff];
        float v2 = v_s[2 * tq + 8][ff];
        float v3 = v_s[2 * tq + 9][ff];
        u32 bh0 = packbf(v0, v1), bh1 = packbf(v2, v3);
        u32 bl0 = packbf(v0 - bf_lo(bh0), v1 - bf_hi(bh0));
        u32 bl1 = packbf(v2 - bf_lo(bh1), v3 - bf_hi(bh1));
        g_frag2[((size_t)jt * 4 + tq) * 128 + ff] =
            make_float4(__uint_as_float(bh0), __uint_as_float(bh1),
                        __uint_as_float(bl0), __uint_as_float(bl1));
    }
}

// ---------------- layer2 aggregation: bf16 m16n8k16, max-trick, 3-buf 1-sync ----------------
__global__ __launch_bounds__(256, 4) void agg2_mma_kernel() {
    __shared__ __align__(16) float4 S4[3][4][130];
    __shared__ __align__(16) float2 ebd_s[3][16];
    int p = blockIdx.x;          // 0..7
    int bi = blockIdx.y * 64;
    int t = threadIdx.x;
    int lane = t & 31, w = t >> 5;
    int g = lane >> 2, tq = lane & 3;
    int it = w >> 1, nth = w & 1;
    int iA = bi + it * 16 + g;
    int iB = iA + 8;
    float2 eA = g_eli2[iA];   // {A, C}
    float2 eB = g_eli2[iB];
    float acc[8][4] = {};
    float lsA = 0.f, lsB = 0.f;

    int jstart = p * (NN / JS2);     // 256 j
    const int NC = (NN / JS2) / 16;  // 16

#define STAGE2(bu, j0) do { \
        int jt0 = (j0) >> 4; \
        _Pragma("unroll") \
        for (int e = t; e < 512; e += 256) { \
            int sq = e >> 7, ff = e & 127; \
            cpa16((u32)__cvta_generic_to_shared(&S4[bu][sq][ff]), \
                  g_frag2 + ((size_t)jt0 * 4 + sq) * 128 + ff); \
        } \
        if (t < 8) cpa16((u32)__cvta_generic_to_shared(&ebd_s[bu][2 * t]), \
                         g_ebd2 + (j0) + 2 * t); \
    } while (0)

    STAGE2(0, jstart);
    CP_COMMIT;
    STAGE2(1, jstart + 16);
    CP_COMMIT;
    for (int c = 0; c < NC; c++) {
        int bu = c % 3;
        if (c + 1 < NC) CP_WAIT1; else CP_WAIT0;
        __syncthreads();
        if (c + 2 < NC) {
            STAGE2((c + 2) % 3, jstart + (c + 2) * 16);
            CP_COMMIT;
        }
        int j0 = jstart + c * 16;
        unsigned wordA = g_bits[(size_t)iA * NWORDS + (j0 >> 5)] >> (j0 & 31);
        unsigned wordB = g_bits[(size_t)iB * NWORDS + (j0 >> 5)] >> (j0 & 31);
        int jb = 2 * tq;
        float2 e1 = ebd_s[bu][jb];
        float2 e2 = ebd_s[bu][jb + 1];
        float2 e3 = ebd_s[bu][jb + 8];
        float2 e4 = ebd_s[bu][jb + 9];
        float wA1 = fmaxf(eA.x * e1.x, eA.y * e1.y);
        float wA2 = fmaxf(eA.x * e2.x, eA.y * e2.y);
        float wA3 = fmaxf(eA.x * e3.x, eA.y * e3.y);
        float wA4 = fmaxf(eA.x * e4.x, eA.y * e4.y);
        float wB1 = fmaxf(eB.x * e1.x, eB.y * e1.y);
        float wB2 = fmaxf(eB.x * e2.x, eB.y * e2.y);
        float wB3 = fmaxf(eB.x * e3.x, eB.y * e3.y);
        float wB4 = fmaxf(eB.x * e4.x, eB.y * e4.y);
        wA1 = ((wordA >> jb) & 1u) ? wA1 : 0.f;
        wA2 = ((wordA >> (jb + 1)) & 1u) ? wA2 : 0.f;
        wA3 = ((wordA >> (jb + 8)) & 1u) ? wA3 : 0.f;
        wA4 = ((wordA >> (jb + 9)) & 1u) ? wA4 : 0.f;
        wB1 = ((wordB >> jb) & 1u) ? wB1 : 0.f;
        wB2 = ((wordB >> (jb + 1)) & 1u) ? wB2 : 0.f;
        wB3 = ((wordB >> (jb + 8)) & 1u) ? wB3 : 0.f;
        wB4 = ((wordB >> (jb + 9)) & 1u) ? wB4 : 0.f;
        lsA += (wA1 + wA2) + (wA3 + wA4);
        lsB += (wB1 + wB2) + (wB3 + wB4);
        u32 ah[4], al4[4];
        ah[0] = packbf(wA1, wA2); ah[1] = packbf(wB1, wB2);
        ah[2] = packbf(wA3, wA4); ah[3] = packbf(wB3, wB4);
        al4[0] = packbf(wA1 - bf_lo(ah[0]), wA2 - bf_hi(ah[0]));
        al4[1] = packbf(wB1 - bf_lo(ah[1]), wB2 - bf_hi(ah[1]));
        al4[2] = packbf(wA3 - bf_lo(ah[2]), wA4 - bf_hi(ah[2]));
        al4[3] = packbf(wB3 - bf_lo(ah[3]), wB4 - bf_hi(ah[3]));
#pragma unroll
        for (int nt = 0; nt < 8; nt++) {
            float4 bfr = S4[bu][tq][(nth * 8 + nt) * 8 + g];
            u32 bh0 = __float_as_uint(bfr.x), bh1 = __float_as_uint(bfr.y);
            u32 bl0 = __float_as_uint(bfr.z), bl1 = __float_as_uint(bfr.w);
            mma16(acc[nt], ah, bh0, bh1);
            mma16(acc[nt], ah, bl0, bl1);
            mma16(acc[nt], al4, bh0, bh1);
        }
    }
    lsA += __shfl_xor_sync(0xffffffffu, lsA, 1);
    lsA += __shfl_xor_sync(0xffffffffu, lsA, 2);
    lsB += __shfl_xor_sync(0xffffffffu, lsB, 1);
    lsB += __shfl_xor_sync(0xffffffffu, lsB, 2);
    if (tq == 0 && nth == 0) {
        g_psum[p * NN + iA] = lsA;
        g_psum[p * NN + iB] = lsB;
    }
    float* pb = g_part + (size_t)p * NN * OUT_F;
#pragma unroll
    for (int nt = 0; nt < 8; nt++) {
        int f = (nth * 8 + nt) * 8 + tq * 2;
        *(float2*)(pb + (size_t)iA * OUT_F + f) = make_float2(acc[nt][0], acc[nt][1]);
        *(float2*)(pb + (size_t)iB * OUT_F + f) = make_float2(acc[nt][2], acc[nt][3]);
    }
}

// ---------------- final reduce + divide ----------------
__global__ void reduce2_kernel(float* __restrict__ out) {
    int i = blockIdx.x;
    int f = threadIdx.x;  // 128
    float num = 0.f, den = 0.f;
#pragma unroll
    for (int p = 0; p < JS2; p++) {
        num += g_part[(size_t)p * NN * OUT_F + (size_t)i * OUT_F + f];
        den += g_psum[p * NN + i];
    }
    out[i * OUT_F + f] = num / den;
}

// ---------------- launch ----------------
extern "C" void kernel_launch(void* const* d_in, const int* in_sizes, int n_in,
                              void* d_out, int out_size) {
    const float* x    = (const float*)d_in[0];
    const float* W1   = (const float*)d_in[1];
    const float* a1_l = (const float*)d_in[2];
    const float* a1_r = (const float*)d_in[3];
    const float* W2   = (const float*)d_in[4];
    const float* a2_l = (const float*)d_in[5];
    const float* a2_r = (const float*)d_in[6];
    const int*   adj  = (const int*)d_in[7];
    float* out = (float*)d_out;

    prep0_kernel<<<NN + 672, 256>>>(adj, x, W1, W2);
    gemm1_mma_kernel<<<dim3(4, 32, KS1G), 256>>>();
    elr1f_kernel<<<dim3(128, 4), 256>>>(a1_l, a1_r);
    agg1_mma_kernel<<<dim3(H1 * JS1, NN / 128), 256>>>();
    reduce1f_kernel<<<dim3(128, 2), 256>>>();
    gemm2_mma_kernel<<<dim3(2, 32, KS2G), 256>>>();
    elr2f_kernel<<<128, 256>>>(a2_l, a2_r);
    agg2_mma_kernel<<<dim3(JS2, NN / 64), 256>>>();
    reduce2_kernel<<<NN, 128>>>(out);
}